// round 15
// baseline (speedup 1.0000x reference)
#include <cuda_runtime.h>
#include <cuda_fp16.h>
#include <math.h>
#include <math_constants.h>

#define NN 100000
#define F1 128
#define H1 4
#define OUTC 10
#define OP 16
#define NG 128
#define NEG_SLOPE 0.2f

#define XS 136   // padded smem stride (halves)
#define WS 136

// ---------------- scratch ----------------
__device__ __align__(16) unsigned char g_h1q[NN * F1];  // layer1 features, e4m3 fp8
__device__ __align__(16) __half g_acc1h[NN * F1];  // fp16 atomic accumulator (init = self-loop term)
__device__ __align__(16) float  g_as1[NN * H1];
__device__ __align__(16) float  g_ad1[NN * H1];
__device__ __align__(16) float  g_den1[NN * H1];

__device__ __align__(16) __half g_h2ph[NN * OP];
__device__ __align__(16) __half g_acc2ph[NN * OP];
__device__ float g_as2[NN];
__device__ float g_ad2[NN];
__device__ float g_den2[NN];

// zero at every launch entry: zero-init covers run 1; final_kernel resets after use.
__device__ float g_pool[NG * OUTC];
__device__ float g_cnt[NG];

// ---------------- helpers ----------------
__device__ __forceinline__ float lrelu(float v) { return v > 0.0f ? v : NEG_SLOPE * v; }
__device__ __forceinline__ float elu_fast(float v) { return v > 0.0f ? v : (__expf(v) - 1.0f); }

__device__ __forceinline__ void pdl_wait() {
    asm volatile("griddepcontrol.wait;" ::: "memory");
}
__device__ __forceinline__ void pdl_trigger() {
    asm volatile("griddepcontrol.launch_dependents;");
}

__device__ __forceinline__ unsigned short f16x2_to_e4m3x2(unsigned h2v) {
    unsigned short r;
    asm("cvt.rn.satfinite.e4m3x2.f16x2 %0, %1;" : "=h"(r) : "r"(h2v));
    return r;
}
__device__ __forceinline__ unsigned e4m3x2_to_f16x2(unsigned short v) {
    unsigned r;
    asm("cvt.rn.f16x2.e4m3x2 %0, %1;" : "=r"(r) : "h"(v));
    return r;
}

__device__ __forceinline__ void mma16816(float c[4],
                                         unsigned a0, unsigned a1, unsigned a2, unsigned a3,
                                         unsigned b0, unsigned b1) {
    asm volatile("mma.sync.aligned.m16n8k16.row.col.f32.f16.f16.f32 "
                 "{%0,%1,%2,%3}, {%4,%5,%6,%7}, {%8,%9}, {%0,%1,%2,%3};"
                 : "+f"(c[0]), "+f"(c[1]), "+f"(c[2]), "+f"(c[3])
                 : "r"(a0), "r"(a1), "r"(a2), "r"(a3), "r"(b0), "r"(b1));
}

// ---------------- GEMM1 (tensor core) + attention dots + self-loop init ----------------
// Fully independent: converts W1 fp32 -> transposed fp16 smem in its own prologue.
__global__ void gemm1_att_kernel(const float* __restrict__ x,
                                 const float* __restrict__ W1,
                                 const float* __restrict__ att_s,
                                 const float* __restrict__ att_d) {
    extern __shared__ __half smem[];
    __half* Wt = smem;                    // [128][WS], Wt[n][k] = W1[k][n]
    __half* xs = smem + F1 * WS;          // [64][XS], later reused as output staging
    float* satt = (float*)(xs + 64 * XS); // [256]: att_s | att_d
    float* exs  = satt + 256;             // [64*4] self-loop exp per (row, head)

    int t = threadIdx.x;
    int row0 = blockIdx.x * 64;

    // W1 convert + transpose: thread handles 2 consecutive k for one n (coalesced loads)
    for (int i = t; i < F1 * F1 / 2; i += 256) {
        int n = i & 127;
        int k2 = i >> 7;             // pair index 0..63
        float a = W1[(2 * k2) * F1 + n];
        float b = W1[(2 * k2 + 1) * F1 + n];
        *(__half2*)&Wt[n * WS + 2 * k2] = __floats2half2_rn(a, b);
    }
    const float4* xv = (const float4*)x;
    for (int i = t; i < 64 * 32; i += 256) {
        int r = i >> 5, c4 = i & 31;
        int gr = row0 + r;
        float4 v = (gr < NN) ? xv[gr * 32 + c4] : make_float4(0, 0, 0, 0);
        __half2 h0 = __floats2half2_rn(v.x, v.y);
        __half2 h1 = __floats2half2_rn(v.z, v.w);
        *(__half2*)&xs[r * XS + c4 * 4]     = h0;
        *(__half2*)&xs[r * XS + c4 * 4 + 2] = h1;
    }
    if (t < 128) { satt[t] = att_s[t]; satt[128 + t] = att_d[t]; }
    __syncthreads();

    int wid = t >> 5, lane = t & 31;
    int wm = wid & 3, wn = wid >> 2;
    int rq = lane >> 2;
    int q2 = (lane & 3) * 2;
    int rA = wm * 16 + rq;

    float c[8][4];
#pragma unroll
    for (int nt = 0; nt < 8; nt++)
#pragma unroll
        for (int j = 0; j < 4; j++) c[nt][j] = 0.0f;

#pragma unroll
    for (int kb = 0; kb < F1; kb += 16) {
        unsigned a0 = *(unsigned*)&xs[rA * XS + kb + q2];
        unsigned a1 = *(unsigned*)&xs[(rA + 8) * XS + kb + q2];
        unsigned a2 = *(unsigned*)&xs[rA * XS + kb + q2 + 8];
        unsigned a3 = *(unsigned*)&xs[(rA + 8) * XS + kb + q2 + 8];
#pragma unroll
        for (int nt = 0; nt < 8; nt++) {
            int n = wn * 64 + nt * 8 + rq;
            unsigned b0 = *(unsigned*)&Wt[n * WS + kb + q2];
            unsigned b1 = *(unsigned*)&Wt[n * WS + kb + q2 + 8];
            mma16816(c[nt], a0, a1, a2, a3, b0, b1);
        }
    }

    __syncthreads();
    __half* es = xs;
#pragma unroll
    for (int nt = 0; nt < 8; nt++) {
        int col = wn * 64 + nt * 8 + q2;
        *(__half2*)&es[rA * XS + col]       = __floats2half2_rn(c[nt][0], c[nt][1]);
        *(__half2*)&es[(rA + 8) * XS + col] = __floats2half2_rn(c[nt][2], c[nt][3]);
    }
    __syncthreads();

    {
        int row = t >> 2, head = t & 3;
        int grow = row0 + row;
        float s = 0.0f, d = 0.0f;
#pragma unroll
        for (int i = 0; i < 16; i++) {
            float2 f = __half22float2(*(__half2*)&es[row * XS + head * 32 + i * 2]);
            s += f.x * satt[head * 32 + i * 2] + f.y * satt[head * 32 + i * 2 + 1];
            d += f.x * satt[128 + head * 32 + i * 2] + f.y * satt[128 + head * 32 + i * 2 + 1];
        }
        float ex = __expf(lrelu(s + d));
        exs[row * 4 + head] = ex;
        if (grow < NN) {
            g_as1[grow * H1 + head] = s;
            g_ad1[grow * H1 + head] = d;
            g_den1[grow * H1 + head] = ex;
        }
    }
    __syncthreads();

    // h1 fp8 store + acc1 init (= ex_self * h1 in fp16), coalesced
#pragma unroll
    for (int j = 0; j < 4; j++) {
        int idx = t * 4 + j;
        int r2 = idx >> 4, c8 = (idx & 15) * 8;
        int gr = row0 + r2;
        if (gr < NN) {
            uint4 raw = *(uint4*)&es[r2 * XS + c8];
            unsigned* rw = (unsigned*)&raw;
            unsigned short q0 = f16x2_to_e4m3x2(rw[0]);
            unsigned short q1 = f16x2_to_e4m3x2(rw[1]);
            unsigned short q2e = f16x2_to_e4m3x2(rw[2]);
            unsigned short q3 = f16x2_to_e4m3x2(rw[3]);
            uint2 qpack;
            qpack.x = (unsigned)q0 | ((unsigned)q1 << 16);
            qpack.y = (unsigned)q2e | ((unsigned)q3 << 16);
            *(uint2*)&g_h1q[gr * F1 + c8] = qpack;
            __half2 ex2 = __float2half2_rn(exs[r2 * 4 + (c8 >> 5)]);
            __half2 a0 = __hmul2(*(__half2*)&rw[0], ex2);
            __half2 a1 = __hmul2(*(__half2*)&rw[1], ex2);
            __half2 a2 = __hmul2(*(__half2*)&rw[2], ex2);
            __half2 a3 = __hmul2(*(__half2*)&rw[3], ex2);
            uint4 out;
            out.x = *(unsigned*)&a0; out.y = *(unsigned*)&a1;
            out.z = *(unsigned*)&a2; out.w = *(unsigned*)&a3;
            *(uint4*)&g_acc1h[gr * F1 + c8] = out;
        }
    }
    pdl_trigger();
}

// ---------------- edge accumulate layer1: 8 lanes per edge, fp8 gather ----------------
__global__ void edge_acc1_kernel(const int* __restrict__ ei, int E_real) {
    int warp = (blockIdx.x * blockDim.x + threadIdx.x) >> 5;
    int lane = threadIdx.x & 31;
    int sub = lane >> 3;
    int sl  = lane & 7;
    int e = warp * 4 + sub;
    bool act = (e < E_real);

    // independent prologue: edge indices (harness input)
    int v = 0;
    if (lane < 8) {
        int ee = warp * 4 + (lane >> 1);
        if (ee < E_real) v = __ldg(&ei[ee + ((lane & 1) ? E_real : 0)]);
    }
    int s = __shfl_sync(0xffffffffu, v, sub * 2);
    int d = __shfl_sync(0xffffffffu, v, sub * 2 + 1);

    pdl_wait();   // as1/ad1/den1/h1q/acc1h produced by gemm1

    float ex = 0.0f;
    if (act && sl < H1) {
        float val = lrelu(g_as1[s * H1 + sl] + g_ad1[d * H1 + sl]);
        ex = __expf(val);
        atomicAdd(&g_den1[d * H1 + sl], ex);
    }
    float exl = __shfl_sync(0xffffffffu, ex, (lane & ~7) + (sl >> 1));
    __half2 ex2 = __float2half2_rn(exl);

    uint4 q = __ldg((const uint4*)&g_h1q[s * F1 + sl * 16]);
    unsigned w0 = q.x, w1 = q.y, w2 = q.z, w3 = q.w;
    __half2 m[8];
    unsigned f;
    f = e4m3x2_to_f16x2((unsigned short)(w0 & 0xffff)); m[0] = __hmul2(*(__half2*)&f, ex2);
    f = e4m3x2_to_f16x2((unsigned short)(w0 >> 16));    m[1] = __hmul2(*(__half2*)&f, ex2);
    f = e4m3x2_to_f16x2((unsigned short)(w1 & 0xffff)); m[2] = __hmul2(*(__half2*)&f, ex2);
    f = e4m3x2_to_f16x2((unsigned short)(w1 >> 16));    m[3] = __hmul2(*(__half2*)&f, ex2);
    f = e4m3x2_to_f16x2((unsigned short)(w2 & 0xffff)); m[4] = __hmul2(*(__half2*)&f, ex2);
    f = e4m3x2_to_f16x2((unsigned short)(w2 >> 16));    m[5] = __hmul2(*(__half2*)&f, ex2);
    f = e4m3x2_to_f16x2((unsigned short)(w3 & 0xffff)); m[6] = __hmul2(*(__half2*)&f, ex2);
    f = e4m3x2_to_f16x2((unsigned short)(w3 >> 16));    m[7] = __hmul2(*(__half2*)&f, ex2);

    if (act) {
        __half* dst = &g_acc1h[d * F1 + sl * 16];
        asm volatile("red.global.add.noftz.v4.f16x2 [%0], {%1,%2,%3,%4};"
                     :: "l"(dst), "r"(*(unsigned*)&m[0]), "r"(*(unsigned*)&m[1]),
                        "r"(*(unsigned*)&m[2]), "r"(*(unsigned*)&m[3]) : "memory");
        asm volatile("red.global.add.noftz.v4.f16x2 [%0], {%1,%2,%3,%4};"
                     :: "l"(dst + 8), "r"(*(unsigned*)&m[4]), "r"(*(unsigned*)&m[5]),
                        "r"(*(unsigned*)&m[6]), "r"(*(unsigned*)&m[7]) : "memory");
    }
    pdl_trigger();
}

// ---------------- layer2 node: dequant+elu -> mma @W2 -> att2 + self-loop init ----------------
__global__ void l2gemm_kernel(const float* __restrict__ W2,
                              const float* __restrict__ b1,
                              const float* __restrict__ att_s2,
                              const float* __restrict__ att_d2) {
    __shared__ __half hs[64 * XS];
    __shared__ __half w2s[OP * WS];
    __shared__ float es[64 * 20];
    __shared__ float b1s[F1];
    __shared__ float satt[2 * OUTC];

    int t = threadIdx.x;
    int row0 = blockIdx.x * 64;

    // independent prologue: W2 convert (fp32 -> transposed fp16 smem), b1, att2
    for (int i = t; i < OP * F1; i += 256) {
        int n = i >> 7, k = i & 127;
        w2s[n * WS + k] = (n < OUTC) ? __float2half(W2[k * OUTC + n]) : __half(0);
    }
    if (t < F1) b1s[t] = b1[t];
    if (t >= 128 && t < 128 + OUTC) satt[t - 128] = att_s2[t - 128];
    if (t >= 160 && t < 160 + OUTC) satt[OUTC + t - 160] = att_d2[t - 160];

    pdl_wait();   // acc1h/den1 produced by edge_acc1
    __syncthreads();

#pragma unroll
    for (int j = 0; j < 4; j++) {
        int chunk = j * 256 + t;
        int r = chunk >> 4, part = chunk & 15;
        int ch0 = part * 8;
        int gr = row0 + r;
        uint4 raw = make_uint4(0, 0, 0, 0);
        float inv = 0.0f;
        if (gr < NN) {
            raw = *(const uint4*)&g_acc1h[gr * F1 + ch0];
            inv = 1.0f / (g_den1[gr * H1 + (part >> 2)] + 1e-16f);
        }
        const unsigned* rw = (const unsigned*)&raw;
        __half2 outp[4];
#pragma unroll
        for (int q = 0; q < 4; q++) {
            float2 fv = __half22float2(*(__half2*)&rw[q]);
            float h0 = elu_fast(fv.x * inv + b1s[ch0 + q * 2]);
            float h1 = elu_fast(fv.y * inv + b1s[ch0 + q * 2 + 1]);
            outp[q] = __floats2half2_rn(h0, h1);
        }
        *(uint4*)&hs[r * XS + ch0] = *(uint4*)outp;
    }
    __syncthreads();

    int wid = t >> 5, lane = t & 31;
    int wm = wid & 3, wn = wid >> 2;
    int rq = lane >> 2;
    int q2 = (lane & 3) * 2;
    int rA = wm * 16 + rq;

    float c[4] = {0, 0, 0, 0};
#pragma unroll
    for (int kb = 0; kb < F1; kb += 16) {
        unsigned a0 = *(unsigned*)&hs[rA * XS + kb + q2];
        unsigned a1 = *(unsigned*)&hs[(rA + 8) * XS + kb + q2];
        unsigned a2 = *(unsigned*)&hs[rA * XS + kb + q2 + 8];
        unsigned a3 = *(unsigned*)&hs[(rA + 8) * XS + kb + q2 + 8];
        int n = wn * 8 + rq;
        unsigned b0 = *(unsigned*)&w2s[n * WS + kb + q2];
        unsigned b1r = *(unsigned*)&w2s[n * WS + kb + q2 + 8];
        mma16816(c, a0, a1, a2, a3, b0, b1r);
    }
    {
        int col = wn * 8 + q2;
        es[rA * 20 + col]           = c[0];
        es[rA * 20 + col + 1]       = c[1];
        es[(rA + 8) * 20 + col]     = c[2];
        es[(rA + 8) * 20 + col + 1] = c[3];
    }
    __syncthreads();

    if (t < 64) {
        int gr = row0 + t;
        if (gr < NN) {
            float as = 0.0f, ad = 0.0f;
            __half2 pk[8];
#pragma unroll
            for (int c2 = 0; c2 < 8; c2++) {
                float lo = (2 * c2 < OUTC)     ? es[t * 20 + 2 * c2]     : 0.0f;
                float hi = (2 * c2 + 1 < OUTC) ? es[t * 20 + 2 * c2 + 1] : 0.0f;
                pk[c2] = __floats2half2_rn(lo, hi);
                if (2 * c2 < OUTC)     { as += lo * satt[2 * c2];     ad += lo * satt[OUTC + 2 * c2]; }
                if (2 * c2 + 1 < OUTC) { as += hi * satt[2 * c2 + 1]; ad += hi * satt[OUTC + 2 * c2 + 1]; }
            }
            *(uint4*)&g_h2ph[gr * OP]     = *(uint4*)&pk[0];
            *(uint4*)&g_h2ph[gr * OP + 8] = *(uint4*)&pk[4];
            g_as2[gr] = as;
            g_ad2[gr] = ad;
            float ex = __expf(lrelu(as + ad));
            g_den2[gr] = ex;
            __half2 ex2 = __float2half2_rn(ex);
            __half2 ak[8];
#pragma unroll
            for (int c2 = 0; c2 < 8; c2++) ak[c2] = __hmul2(pk[c2], ex2);
            *(uint4*)&g_acc2ph[gr * OP]     = *(uint4*)&ak[0];
            *(uint4*)&g_acc2ph[gr * OP + 8] = *(uint4*)&ak[4];
        }
    }
    pdl_trigger();
}

// ---------------- edge accumulate layer2: 2 lanes per edge ----------------
__global__ void edge_acc2_kernel(const int* __restrict__ ei, int E_real) {
    int warp = (blockIdx.x * blockDim.x + threadIdx.x) >> 5;
    int lane = threadIdx.x & 31;
    int li = lane & 1;
    int ee = warp * 16 + (lane >> 1);
    bool act = (ee < E_real);

    // independent prologue: edge indices
    int v = 0;
    if (act) v = __ldg(&ei[ee + (li ? E_real : 0)]);
    int s = __shfl_sync(0xffffffffu, v, lane & ~1);
    int d = __shfl_sync(0xffffffffu, v, lane | 1);

    pdl_wait();   // as2/ad2/den2/h2ph/acc2ph produced by l2gemm

    float ex = 0.0f;
    if (act && li == 0) {
        ex = __expf(lrelu(g_as2[s] + g_ad2[d]));
        atomicAdd(&g_den2[d], ex);
    }
    ex = __shfl_sync(0xffffffffu, ex, lane & ~1);
    __half2 ex2 = __float2half2_rn(ex);
    uint4 raw = __ldg((const uint4*)&g_h2ph[s * OP + li * 8]);
    __half2 m0 = __hmul2(*(__half2*)&raw.x, ex2);
    __half2 m1 = __hmul2(*(__half2*)&raw.y, ex2);
    __half2 m2 = __hmul2(*(__half2*)&raw.z, ex2);
    __half2 m3 = __hmul2(*(__half2*)&raw.w, ex2);
    if (act) {
        __half* dst = &g_acc2ph[d * OP + li * 8];
        asm volatile("red.global.add.noftz.v4.f16x2 [%0], {%1,%2,%3,%4};"
                     :: "l"(dst), "r"(*(unsigned*)&m0), "r"(*(unsigned*)&m1),
                        "r"(*(unsigned*)&m2), "r"(*(unsigned*)&m3) : "memory");
    }
    pdl_trigger();
}

// ---------------- finalize layer2 + pooling (warp-aggregated atomics) ----------------
__global__ void fin2pool_kernel(const float* __restrict__ b2, const int* __restrict__ batch) {
    int n = blockIdx.x * blockDim.x + threadIdx.x;
    if (n >= NN) return;
    int lane = threadIdx.x & 31;
    int g = batch[n];   // independent input

    pdl_wait();   // den2/acc2ph produced by edge_acc2

    float inv = 1.0f / (g_den2[n] + 1e-16f);
    float v[OUTC];
#pragma unroll
    for (int c = 0; c < OUTC; c++)
        v[c] = elu_fast(__half2float(g_acc2ph[n * OP + c]) * inv + b2[c]);

    int g0 = __shfl_sync(0xffffffffu, g, 0);
    bool uniform = __all_sync(0xffffffffu, g == g0);
    if (uniform) {
#pragma unroll
        for (int o = 16; o; o >>= 1)
#pragma unroll
            for (int c = 0; c < OUTC; c++)
                v[c] += __shfl_xor_sync(0xffffffffu, v[c], o);
        if (lane == 0) {
#pragma unroll
            for (int c = 0; c < OUTC; c++)
                atomicAdd(&g_pool[g0 * OUTC + c], v[c]);
            atomicAdd(&g_cnt[g0], 32.0f);
        }
    } else {
#pragma unroll
        for (int c = 0; c < OUTC; c++)
            atomicAdd(&g_pool[g * OUTC + c], v[c]);
        atomicAdd(&g_cnt[g], 1.0f);
    }
    pdl_trigger();
}

// ---------------- final: mean + log_softmax + pool/cnt reset ----------------
__global__ void final_kernel(float* __restrict__ out) {
    int g = threadIdx.x;
    if (g >= NG) return;
    pdl_wait();
    float cnt = fmaxf(g_cnt[g], 1.0f);
    float p[OUTC];
    float mx = -CUDART_INF_F;
#pragma unroll
    for (int c = 0; c < OUTC; c++) {
        p[c] = g_pool[g * OUTC + c] / cnt;
        mx = fmaxf(mx, p[c]);
    }
    float se = 0.0f;
#pragma unroll
    for (int c = 0; c < OUTC; c++) se += __expf(p[c] - mx);
    float lse = mx + __logf(se);
#pragma unroll
    for (int c = 0; c < OUTC; c++) {
        out[g * OUTC + c] = p[c] - lse;
        g_pool[g * OUTC + c] = 0.0f;   // reset for next launch (graph replay)
    }
    g_cnt[g] = 0.0f;
}

// ---------------- PDL launch helper ----------------
template <typename F, typename... Args>
static void launch_pdl(F kern, dim3 grid, dim3 block, size_t smem, Args... args) {
    cudaLaunchConfig_t cfg = {};
    cfg.gridDim = grid;
    cfg.blockDim = block;
    cfg.dynamicSmemBytes = smem;
    cudaLaunchAttribute attr[1];
    attr[0].id = cudaLaunchAttributeProgrammaticStreamSerialization;
    attr[0].val.programmaticStreamSerializationAllowed = 1;
    cfg.attrs = attr;
    cfg.numAttrs = 1;
    cudaLaunchKernelEx(&cfg, kern, args...);
}

// ---------------- launch ----------------
extern "C" void kernel_launch(void* const* d_in, const int* in_sizes, int n_in,
                              void* d_out, int out_size) {
    const float* x      = (const float*)d_in[0];
    const float* W1     = (const float*)d_in[1];
    const float* att_s1 = (const float*)d_in[2];
    const float* att_d1 = (const float*)d_in[3];
    const float* b1     = (const float*)d_in[4];
    const float* W2     = (const float*)d_in[5];
    const float* att_s2 = (const float*)d_in[6];
    const float* att_d2 = (const float*)d_in[7];
    const float* b2     = (const float*)d_in[8];
    const int*   ei     = (const int*)d_in[9];
    const int*   batch  = (const int*)d_in[10];
    float* out = (float*)d_out;

    int E_real = in_sizes[9] / 2;

    int gemm_smem = (F1 * WS + 64 * XS) * (int)sizeof(__half) + 512 * (int)sizeof(float);
    cudaFuncSetAttribute(gemm1_att_kernel, cudaFuncAttributeMaxDynamicSharedMemorySize, gemm_smem);
    gemm1_att_kernel<<<(NN + 63) / 64, 256, gemm_smem>>>(x, W1, att_s1, att_d1);

    long long w1 = ((long long)E_real + 3) / 4;
    launch_pdl(edge_acc1_kernel, dim3((unsigned)((w1 * 32 + 255) / 256)), dim3(256), (size_t)0,
               ei, E_real);

    launch_pdl(l2gemm_kernel, dim3((NN + 63) / 64), dim3(256), (size_t)0,
               W2, b1, att_s2, att_d2);

    long long w2 = ((long long)E_real + 15) / 16;
    launch_pdl(edge_acc2_kernel, dim3((unsigned)((w2 * 32 + 255) / 256)), dim3(256), (size_t)0,
               ei, E_real);

    launch_pdl(fin2pool_kernel, dim3((NN + 255) / 256), dim3(256), (size_t)0,
               b2, batch);

    launch_pdl(final_kernel, dim3(1), dim3(NG), (size_t)0, out);
}

// round 16
// speedup vs baseline: 1.0179x; 1.0179x over previous
#include <cuda_runtime.h>
#include <cuda_fp16.h>
#include <math.h>
#include <math_constants.h>

#define NN 100000
#define F1 128
#define H1 4
#define OUTC 10
#define OP 16
#define NG 128
#define NEG_SLOPE 0.2f

#define XS 136   // padded smem stride (halves)
#define WS 136

#define POOL_BLOCKS ((NN + 255) / 256)

// ---------------- scratch ----------------
__device__ __align__(16) unsigned char g_h1q[NN * F1];  // layer1 features, e4m3 fp8
__device__ __align__(16) __half g_acc1h[NN * F1];  // fp16 atomic accumulator (init = self-loop term)
__device__ __align__(16) float  g_as1[NN * H1];
__device__ __align__(16) float  g_ad1[NN * H1];
__device__ __align__(16) float  g_den1[NN * H1];

__device__ __align__(16) __half g_W1h[F1 * F1];    // W1 transposed [n][k], fp16

__device__ __align__(16) __half g_h2ph[NN * OP];
__device__ __align__(16) __half g_acc2ph[NN * OP];
__device__ float g_as2[NN];
__device__ float g_ad2[NN];
__device__ float g_den2[NN];

__device__ float g_pool[NG * OUTC];
__device__ float g_cnt[NG];
__device__ unsigned g_done;   // zero-init; reset by finalizing block each launch

// ---------------- helpers ----------------
__device__ __forceinline__ float lrelu(float v) { return v > 0.0f ? v : NEG_SLOPE * v; }
__device__ __forceinline__ float elu_fast(float v) { return v > 0.0f ? v : (__expf(v) - 1.0f); }

__device__ __forceinline__ void pdl_wait() {
    asm volatile("griddepcontrol.wait;" ::: "memory");
}
__device__ __forceinline__ void pdl_trigger() {
    asm volatile("griddepcontrol.launch_dependents;");
}

__device__ __forceinline__ unsigned short f16x2_to_e4m3x2(unsigned h2v) {
    unsigned short r;
    asm("cvt.rn.satfinite.e4m3x2.f16x2 %0, %1;" : "=h"(r) : "r"(h2v));
    return r;
}
__device__ __forceinline__ unsigned e4m3x2_to_f16x2(unsigned short v) {
    unsigned r;
    asm("cvt.rn.f16x2.e4m3x2 %0, %1;" : "=r"(r) : "h"(v));
    return r;
}

__device__ __forceinline__ void mma16816(float c[4],
                                         unsigned a0, unsigned a1, unsigned a2, unsigned a3,
                                         unsigned b0, unsigned b1) {
    asm volatile("mma.sync.aligned.m16n8k16.row.col.f32.f16.f16.f32 "
                 "{%0,%1,%2,%3}, {%4,%5,%6,%7}, {%8,%9}, {%0,%1,%2,%3};"
                 : "+f"(c[0]), "+f"(c[1]), "+f"(c[2]), "+f"(c[3])
                 : "r"(a0), "r"(a1), "r"(a2), "r"(a3), "r"(b0), "r"(b1));
}

// ---------------- setup: W1 convert + pool/cnt zero ----------------
__global__ void convert_w_kernel(const float* __restrict__ W1) {
    int t = blockIdx.x * blockDim.x + threadIdx.x;
    if (t < F1 * F1) {
        int n = t >> 7, k = t & 127;
        g_W1h[t] = __float2half(W1[k * F1 + n]);
    }
    if (t < NG * OUTC) g_pool[t] = 0.0f;
    if (t < NG) g_cnt[t] = 0.0f;
    pdl_trigger();
}

// ---------------- GEMM1 (tensor core) + attention dots + self-loop init ----------------
__global__ void gemm1_att_kernel(const float* __restrict__ x,
                                 const float* __restrict__ att_s,
                                 const float* __restrict__ att_d) {
    extern __shared__ __half smem[];
    __half* Wt = smem;                    // [128][WS]
    __half* xs = smem + F1 * WS;          // [64][XS], later reused as output staging
    float* satt = (float*)(xs + 64 * XS); // [256]: att_s | att_d
    float* exs  = satt + 256;             // [64*4] self-loop exp per (row, head)

    int t = threadIdx.x;
    int row0 = blockIdx.x * 64;

    // independent prologue: x tile + att vectors (harness inputs)
    const float4* xv = (const float4*)x;
    for (int i = t; i < 64 * 32; i += 256) {
        int r = i >> 5, c4 = i & 31;
        int gr = row0 + r;
        float4 v = (gr < NN) ? xv[gr * 32 + c4] : make_float4(0, 0, 0, 0);
        __half2 h0 = __floats2half2_rn(v.x, v.y);
        __half2 h1 = __floats2half2_rn(v.z, v.w);
        *(__half2*)&xs[r * XS + c4 * 4]     = h0;
        *(__half2*)&xs[r * XS + c4 * 4 + 2] = h1;
    }
    if (t < 128) { satt[t] = att_s[t]; satt[128 + t] = att_d[t]; }

    pdl_wait();   // g_W1h produced by convert_w

    const uint4* wsrc = (const uint4*)g_W1h;
    for (int i = t; i < F1 * F1 / 8; i += 256) {
        int n = i >> 4, kc = (i & 15) * 8;
        *(uint4*)&Wt[n * WS + kc] = wsrc[i];
    }
    __syncthreads();

    int wid = t >> 5, lane = t & 31;
    int wm = wid & 3, wn = wid >> 2;
    int rq = lane >> 2;
    int q2 = (lane & 3) * 2;
    int rA = wm * 16 + rq;

    float c[8][4];
#pragma unroll
    for (int nt = 0; nt < 8; nt++)
#pragma unroll
        for (int j = 0; j < 4; j++) c[nt][j] = 0.0f;

#pragma unroll
    for (int kb = 0; kb < F1; kb += 16) {
        unsigned a0 = *(unsigned*)&xs[rA * XS + kb + q2];
        unsigned a1 = *(unsigned*)&xs[(rA + 8) * XS + kb + q2];
        unsigned a2 = *(unsigned*)&xs[rA * XS + kb + q2 + 8];
        unsigned a3 = *(unsigned*)&xs[(rA + 8) * XS + kb + q2 + 8];
#pragma unroll
        for (int nt = 0; nt < 8; nt++) {
            int n = wn * 64 + nt * 8 + rq;
            unsigned b0 = *(unsigned*)&Wt[n * WS + kb + q2];
            unsigned b1 = *(unsigned*)&Wt[n * WS + kb + q2 + 8];
            mma16816(c[nt], a0, a1, a2, a3, b0, b1);
        }
    }

    __syncthreads();
    __half* es = xs;
#pragma unroll
    for (int nt = 0; nt < 8; nt++) {
        int col = wn * 64 + nt * 8 + q2;
        *(__half2*)&es[rA * XS + col]       = __floats2half2_rn(c[nt][0], c[nt][1]);
        *(__half2*)&es[(rA + 8) * XS + col] = __floats2half2_rn(c[nt][2], c[nt][3]);
    }
    __syncthreads();

    {
        int row = t >> 2, head = t & 3;
        int grow = row0 + row;
        float s = 0.0f, d = 0.0f;
#pragma unroll
        for (int i = 0; i < 16; i++) {
            float2 f = __half22float2(*(__half2*)&es[row * XS + head * 32 + i * 2]);
            s += f.x * satt[head * 32 + i * 2] + f.y * satt[head * 32 + i * 2 + 1];
            d += f.x * satt[128 + head * 32 + i * 2] + f.y * satt[128 + head * 32 + i * 2 + 1];
        }
        float ex = __expf(lrelu(s + d));
        exs[row * 4 + head] = ex;
        if (grow < NN) {
            g_as1[grow * H1 + head] = s;
            g_ad1[grow * H1 + head] = d;
            g_den1[grow * H1 + head] = ex;
        }
    }
    __syncthreads();

    // h1 fp8 store + acc1 init (= ex_self * h1 in fp16), coalesced
#pragma unroll
    for (int j = 0; j < 4; j++) {
        int idx = t * 4 + j;
        int r2 = idx >> 4, c8 = (idx & 15) * 8;
        int gr = row0 + r2;
        if (gr < NN) {
            uint4 raw = *(uint4*)&es[r2 * XS + c8];
            unsigned* rw = (unsigned*)&raw;
            unsigned short q0 = f16x2_to_e4m3x2(rw[0]);
            unsigned short q1 = f16x2_to_e4m3x2(rw[1]);
            unsigned short q2e = f16x2_to_e4m3x2(rw[2]);
            unsigned short q3 = f16x2_to_e4m3x2(rw[3]);
            uint2 qpack;
            qpack.x = (unsigned)q0 | ((unsigned)q1 << 16);
            qpack.y = (unsigned)q2e | ((unsigned)q3 << 16);
            *(uint2*)&g_h1q[gr * F1 + c8] = qpack;
            __half2 ex2 = __float2half2_rn(exs[r2 * 4 + (c8 >> 5)]);
            __half2 a0 = __hmul2(*(__half2*)&rw[0], ex2);
            __half2 a1 = __hmul2(*(__half2*)&rw[1], ex2);
            __half2 a2 = __hmul2(*(__half2*)&rw[2], ex2);
            __half2 a3 = __hmul2(*(__half2*)&rw[3], ex2);
            uint4 out;
            out.x = *(unsigned*)&a0; out.y = *(unsigned*)&a1;
            out.z = *(unsigned*)&a2; out.w = *(unsigned*)&a3;
            *(uint4*)&g_acc1h[gr * F1 + c8] = out;
        }
    }
    pdl_trigger();
}

// ---------------- edge accumulate layer1: 8 lanes per edge, fp8 gather ----------------
__global__ void edge_acc1_kernel(const int* __restrict__ ei, int E_real) {
    int warp = (blockIdx.x * blockDim.x + threadIdx.x) >> 5;
    int lane = threadIdx.x & 31;
    int sub = lane >> 3;
    int sl  = lane & 7;
    int e = warp * 4 + sub;
    bool act = (e < E_real);

    // independent prologue: edge indices (harness input)
    int v = 0;
    if (lane < 8) {
        int ee = warp * 4 + (lane >> 1);
        if (ee < E_real) v = __ldg(&ei[ee + ((lane & 1) ? E_real : 0)]);
    }
    int s = __shfl_sync(0xffffffffu, v, sub * 2);
    int d = __shfl_sync(0xffffffffu, v, sub * 2 + 1);

    pdl_wait();   // as1/ad1/den1/h1q/acc1h produced by gemm1

    float ex = 0.0f;
    if (act && sl < H1) {
        float val = lrelu(g_as1[s * H1 + sl] + g_ad1[d * H1 + sl]);
        ex = __expf(val);
        atomicAdd(&g_den1[d * H1 + sl], ex);
    }
    float exl = __shfl_sync(0xffffffffu, ex, (lane & ~7) + (sl >> 1));
    __half2 ex2 = __float2half2_rn(exl);

    uint4 q = __ldg((const uint4*)&g_h1q[s * F1 + sl * 16]);
    unsigned w0 = q.x, w1 = q.y, w2 = q.z, w3 = q.w;
    __half2 m[8];
    unsigned f;
    f = e4m3x2_to_f16x2((unsigned short)(w0 & 0xffff)); m[0] = __hmul2(*(__half2*)&f, ex2);
    f = e4m3x2_to_f16x2((unsigned short)(w0 >> 16));    m[1] = __hmul2(*(__half2*)&f, ex2);
    f = e4m3x2_to_f16x2((unsigned short)(w1 & 0xffff)); m[2] = __hmul2(*(__half2*)&f, ex2);
    f = e4m3x2_to_f16x2((unsigned short)(w1 >> 16));    m[3] = __hmul2(*(__half2*)&f, ex2);
    f = e4m3x2_to_f16x2((unsigned short)(w2 & 0xffff)); m[4] = __hmul2(*(__half2*)&f, ex2);
    f = e4m3x2_to_f16x2((unsigned short)(w2 >> 16));    m[5] = __hmul2(*(__half2*)&f, ex2);
    f = e4m3x2_to_f16x2((unsigned short)(w3 & 0xffff)); m[6] = __hmul2(*(__half2*)&f, ex2);
    f = e4m3x2_to_f16x2((unsigned short)(w3 >> 16));    m[7] = __hmul2(*(__half2*)&f, ex2);

    if (act) {
        __half* dst = &g_acc1h[d * F1 + sl * 16];
        asm volatile("red.global.add.noftz.v4.f16x2 [%0], {%1,%2,%3,%4};"
                     :: "l"(dst), "r"(*(unsigned*)&m[0]), "r"(*(unsigned*)&m[1]),
                        "r"(*(unsigned*)&m[2]), "r"(*(unsigned*)&m[3]) : "memory");
        asm volatile("red.global.add.noftz.v4.f16x2 [%0], {%1,%2,%3,%4};"
                     :: "l"(dst + 8), "r"(*(unsigned*)&m[4]), "r"(*(unsigned*)&m[5]),
                        "r"(*(unsigned*)&m[6]), "r"(*(unsigned*)&m[7]) : "memory");
    }
    pdl_trigger();
}

// ---------------- layer2 node: dequant+elu -> mma @W2 -> att2 + self-loop init ----------------
__global__ void l2gemm_kernel(const float* __restrict__ W2,
                              const float* __restrict__ b1,
                              const float* __restrict__ att_s2,
                              const float* __restrict__ att_d2) {
    __shared__ __half hs[64 * XS];
    __shared__ __half w2s[OP * WS];
    __shared__ float es[64 * 20];
    __shared__ float b1s[F1];
    __shared__ float satt[2 * OUTC];

    int t = threadIdx.x;
    int row0 = blockIdx.x * 64;

    // independent prologue: W2 convert (fp32 -> transposed fp16 smem), b1, att2
    for (int i = t; i < OP * F1; i += 256) {
        int n = i >> 7, k = i & 127;
        w2s[n * WS + k] = (n < OUTC) ? __float2half(W2[k * OUTC + n]) : __half(0);
    }
    if (t < F1) b1s[t] = b1[t];
    if (t >= 128 && t < 128 + OUTC) satt[t - 128] = att_s2[t - 128];
    if (t >= 160 && t < 160 + OUTC) satt[OUTC + t - 160] = att_d2[t - 160];

    pdl_wait();   // acc1h/den1 produced by edge_acc1
    __syncthreads();

#pragma unroll
    for (int j = 0; j < 4; j++) {
        int chunk = j * 256 + t;
        int r = chunk >> 4, part = chunk & 15;
        int ch0 = part * 8;
        int gr = row0 + r;
        uint4 raw = make_uint4(0, 0, 0, 0);
        float inv = 0.0f;
        if (gr < NN) {
            raw = *(const uint4*)&g_acc1h[gr * F1 + ch0];
            inv = 1.0f / (g_den1[gr * H1 + (part >> 2)] + 1e-16f);
        }
        const unsigned* rw = (const unsigned*)&raw;
        __half2 outp[4];
#pragma unroll
        for (int q = 0; q < 4; q++) {
            float2 fv = __half22float2(*(__half2*)&rw[q]);
            float h0 = elu_fast(fv.x * inv + b1s[ch0 + q * 2]);
            float h1 = elu_fast(fv.y * inv + b1s[ch0 + q * 2 + 1]);
            outp[q] = __floats2half2_rn(h0, h1);
        }
        *(uint4*)&hs[r * XS + ch0] = *(uint4*)outp;
    }
    __syncthreads();

    int wid = t >> 5, lane = t & 31;
    int wm = wid & 3, wn = wid >> 2;
    int rq = lane >> 2;
    int q2 = (lane & 3) * 2;
    int rA = wm * 16 + rq;

    float c[4] = {0, 0, 0, 0};
#pragma unroll
    for (int kb = 0; kb < F1; kb += 16) {
        unsigned a0 = *(unsigned*)&hs[rA * XS + kb + q2];
        unsigned a1 = *(unsigned*)&hs[(rA + 8) * XS + kb + q2];
        unsigned a2 = *(unsigned*)&hs[rA * XS + kb + q2 + 8];
        unsigned a3 = *(unsigned*)&hs[(rA + 8) * XS + kb + q2 + 8];
        int n = wn * 8 + rq;
        unsigned b0 = *(unsigned*)&w2s[n * WS + kb + q2];
        unsigned b1r = *(unsigned*)&w2s[n * WS + kb + q2 + 8];
        mma16816(c, a0, a1, a2, a3, b0, b1r);
    }
    {
        int col = wn * 8 + q2;
        es[rA * 20 + col]           = c[0];
        es[rA * 20 + col + 1]       = c[1];
        es[(rA + 8) * 20 + col]     = c[2];
        es[(rA + 8) * 20 + col + 1] = c[3];
    }
    __syncthreads();

    if (t < 64) {
        int gr = row0 + t;
        if (gr < NN) {
            float as = 0.0f, ad = 0.0f;
            __half2 pk[8];
#pragma unroll
            for (int c2 = 0; c2 < 8; c2++) {
                float lo = (2 * c2 < OUTC)     ? es[t * 20 + 2 * c2]     : 0.0f;
                float hi = (2 * c2 + 1 < OUTC) ? es[t * 20 + 2 * c2 + 1] : 0.0f;
                pk[c2] = __floats2half2_rn(lo, hi);
                if (2 * c2 < OUTC)     { as += lo * satt[2 * c2];     ad += lo * satt[OUTC + 2 * c2]; }
                if (2 * c2 + 1 < OUTC) { as += hi * satt[2 * c2 + 1]; ad += hi * satt[OUTC + 2 * c2 + 1]; }
            }
            *(uint4*)&g_h2ph[gr * OP]     = *(uint4*)&pk[0];
            *(uint4*)&g_h2ph[gr * OP + 8] = *(uint4*)&pk[4];
            g_as2[gr] = as;
            g_ad2[gr] = ad;
            float ex = __expf(lrelu(as + ad));
            g_den2[gr] = ex;
            __half2 ex2 = __float2half2_rn(ex);
            __half2 ak[8];
#pragma unroll
            for (int c2 = 0; c2 < 8; c2++) ak[c2] = __hmul2(pk[c2], ex2);
            *(uint4*)&g_acc2ph[gr * OP]     = *(uint4*)&ak[0];
            *(uint4*)&g_acc2ph[gr * OP + 8] = *(uint4*)&ak[4];
        }
    }
    pdl_trigger();
}

// ---------------- edge accumulate layer2: 2 lanes per edge ----------------
__global__ void edge_acc2_kernel(const int* __restrict__ ei, int E_real) {
    int warp = (blockIdx.x * blockDim.x + threadIdx.x) >> 5;
    int lane = threadIdx.x & 31;
    int li = lane & 1;
    int ee = warp * 16 + (lane >> 1);
    bool act = (ee < E_real);

    // independent prologue: edge indices
    int v = 0;
    if (act) v = __ldg(&ei[ee + (li ? E_real : 0)]);
    int s = __shfl_sync(0xffffffffu, v, lane & ~1);
    int d = __shfl_sync(0xffffffffu, v, lane | 1);

    pdl_wait();   // as2/ad2/den2/h2ph/acc2ph produced by l2gemm

    float ex = 0.0f;
    if (act && li == 0) {
        ex = __expf(lrelu(g_as2[s] + g_ad2[d]));
        atomicAdd(&g_den2[d], ex);
    }
    ex = __shfl_sync(0xffffffffu, ex, lane & ~1);
    __half2 ex2 = __float2half2_rn(ex);
    uint4 raw = __ldg((const uint4*)&g_h2ph[s * OP + li * 8]);
    __half2 m0 = __hmul2(*(__half2*)&raw.x, ex2);
    __half2 m1 = __hmul2(*(__half2*)&raw.y, ex2);
    __half2 m2 = __hmul2(*(__half2*)&raw.z, ex2);
    __half2 m3 = __hmul2(*(__half2*)&raw.w, ex2);
    if (act) {
        __half* dst = &g_acc2ph[d * OP + li * 8];
        asm volatile("red.global.add.noftz.v4.f16x2 [%0], {%1,%2,%3,%4};"
                     :: "l"(dst), "r"(*(unsigned*)&m0), "r"(*(unsigned*)&m1),
                        "r"(*(unsigned*)&m2), "r"(*(unsigned*)&m3) : "memory");
    }
    pdl_trigger();
}

// ---------------- finalize layer2 + pooling + (last block) log_softmax ----------------
__global__ void fin2pool_kernel(const float* __restrict__ b2, const int* __restrict__ batch,
                                float* __restrict__ out) {
    __shared__ unsigned s_last;
    int n = blockIdx.x * blockDim.x + threadIdx.x;
    int t = threadIdx.x;
    int lane = t & 31;
    int g = (n < NN) ? batch[n] : 0;   // independent input

    pdl_wait();   // den2/acc2ph produced by edge_acc2

    if (n < NN) {
        float inv = 1.0f / (g_den2[n] + 1e-16f);
        float v[OUTC];
#pragma unroll
        for (int c = 0; c < OUTC; c++)
            v[c] = elu_fast(__half2float(g_acc2ph[n * OP + c]) * inv + b2[c]);

        int g0 = __shfl_sync(0xffffffffu, g, 0);
        bool uniform = __all_sync(0xffffffffu, g == g0);
        if (uniform) {
#pragma unroll
            for (int o = 16; o; o >>= 1)
#pragma unroll
                for (int c = 0; c < OUTC; c++)
                    v[c] += __shfl_xor_sync(0xffffffffu, v[c], o);
            if (lane == 0) {
#pragma unroll
                for (int c = 0; c < OUTC; c++)
                    atomicAdd(&g_pool[g0 * OUTC + c], v[c]);
                atomicAdd(&g_cnt[g0], 32.0f);
            }
        } else {
#pragma unroll
            for (int c = 0; c < OUTC; c++)
                atomicAdd(&g_pool[g * OUTC + c], v[c]);
            atomicAdd(&g_cnt[g], 1.0f);
        }
    }

    // last-block: finalize log_softmax (all blocks' atomics are visible once
    // every block has fenced + incremented the counter)
    __syncthreads();
    if (t == 0) {
        __threadfence();
        unsigned prev = atomicAdd(&g_done, 1u);
        s_last = (prev == (unsigned)(POOL_BLOCKS - 1)) ? 1u : 0u;
    }
    __syncthreads();
    if (s_last && t < NG) {
        int gg = t;
        float cnt = fmaxf(g_cnt[gg], 1.0f);
        float p[OUTC];
        float mx = -CUDART_INF_F;
#pragma unroll
        for (int c = 0; c < OUTC; c++) {
            p[c] = g_pool[gg * OUTC + c] / cnt;
            mx = fmaxf(mx, p[c]);
        }
        float se = 0.0f;
#pragma unroll
        for (int c = 0; c < OUTC; c++) se += __expf(p[c] - mx);
        float lse = mx + __logf(se);
#pragma unroll
        for (int c = 0; c < OUTC; c++) out[gg * OUTC + c] = p[c] - lse;
        if (gg == 0) g_done = 0;   // reset counter for next launch (graph replay)
    }
}

// ---------------- PDL launch helper ----------------
template <typename F, typename... Args>
static void launch_pdl(F kern, dim3 grid, dim3 block, size_t smem, Args... args) {
    cudaLaunchConfig_t cfg = {};
    cfg.gridDim = grid;
    cfg.blockDim = block;
    cfg.dynamicSmemBytes = smem;
    cudaLaunchAttribute attr[1];
    attr[0].id = cudaLaunchAttributeProgrammaticStreamSerialization;
    attr[0].val.programmaticStreamSerializationAllowed = 1;
    cfg.attrs = attr;
    cfg.numAttrs = 1;
    cudaLaunchKernelEx(&cfg, kern, args...);
}

// ---------------- launch ----------------
extern "C" void kernel_launch(void* const* d_in, const int* in_sizes, int n_in,
                              void* d_out, int out_size) {
    const float* x      = (const float*)d_in[0];
    const float* W1     = (const float*)d_in[1];
    const float* att_s1 = (const float*)d_in[2];
    const float* att_d1 = (const float*)d_in[3];
    const float* b1     = (const float*)d_in[4];
    const float* W2     = (const float*)d_in[5];
    const float* att_s2 = (const float*)d_in[6];
    const float* att_d2 = (const float*)d_in[7];
    const float* b2     = (const float*)d_in[8];
    const int*   ei     = (const int*)d_in[9];
    const int*   batch  = (const int*)d_in[10];
    float* out = (float*)d_out;

    int E_real = in_sizes[9] / 2;

    convert_w_kernel<<<(F1 * F1 + 255) / 256, 256>>>(W1);

    int gemm_smem = (F1 * WS + 64 * XS) * (int)sizeof(__half) + 512 * (int)sizeof(float);
    cudaFuncSetAttribute(gemm1_att_kernel, cudaFuncAttributeMaxDynamicSharedMemorySize, gemm_smem);
    launch_pdl(gemm1_att_kernel, dim3((NN + 63) / 64), dim3(256), (size_t)gemm_smem,
               x, att_s1, att_d1);

    long long w1 = ((long long)E_real + 3) / 4;
    launch_pdl(edge_acc1_kernel, dim3((unsigned)((w1 * 32 + 255) / 256)), dim3(256), (size_t)0,
               ei, E_real);

    launch_pdl(l2gemm_kernel, dim3((NN + 63) / 64), dim3(256), (size_t)0,
               W2, b1, att_s2, att_d2);

    long long w2 = ((long long)E_real + 15) / 16;
    launch_pdl(edge_acc2_kernel, dim3((unsigned)((w2 * 32 + 255) / 256)), dim3(256), (size_t)0,
               ei, E_real);

    launch_pdl(fin2pool_kernel, dim3(POOL_BLOCKS), dim3(256), (size_t)0,
               b2, batch, out);
}

// round 17
// speedup vs baseline: 1.0433x; 1.0249x over previous
#include <cuda_runtime.h>
#include <cuda_fp16.h>
#include <math.h>
#include <math_constants.h>

#define NN 100000
#define F1 128
#define H1 4
#define OUTC 10
#define OP 16
#define NG 128
#define NEG_SLOPE 0.2f

#define XS 136   // padded smem stride (halves)
#define WS 136

#define POOL_BLOCKS ((NN + 255) / 256)

// ---------------- scratch ----------------
__device__ __align__(16) unsigned char g_h1q[NN * F1];  // layer1 features, e4m3 fp8
__device__ __align__(16) __half g_acc1h[NN * F1];  // fp16 atomic accumulator (init = self-loop term)
__device__ __align__(16) float  g_as1[NN * H1];
__device__ __align__(16) float  g_ad1[NN * H1];
__device__ __align__(16) float  g_den1[NN * H1];

__device__ __align__(16) __half g_W1h[F1 * F1];    // W1 transposed [n][k], fp16

// h2ph row layout (16 halves): ch0-9 = h2 fp16, ch10-11 = as2 fp32 bits, ch12-13 = ad2 fp32 bits, ch14-15 = 0
__device__ __align__(16) __half g_h2ph[NN * OP];
__device__ __align__(16) __half g_acc2ph[NN * OP];
__device__ float g_ad2[NN];
__device__ float g_den2[NN];

__device__ float g_pool[NG * OUTC];
__device__ float g_cnt[NG];
__device__ unsigned g_done;   // zero-init; reset by finalizing block each launch

// ---------------- helpers ----------------
__device__ __forceinline__ float lrelu(float v) { return v > 0.0f ? v : NEG_SLOPE * v; }
__device__ __forceinline__ float elu_fast(float v) { return v > 0.0f ? v : (__expf(v) - 1.0f); }

__device__ __forceinline__ void pdl_wait() {
    asm volatile("griddepcontrol.wait;" ::: "memory");
}
__device__ __forceinline__ void pdl_trigger() {
    asm volatile("griddepcontrol.launch_dependents;");
}

__device__ __forceinline__ unsigned short f16x2_to_e4m3x2(unsigned h2v) {
    unsigned short r;
    asm("cvt.rn.satfinite.e4m3x2.f16x2 %0, %1;" : "=h"(r) : "r"(h2v));
    return r;
}
__device__ __forceinline__ unsigned e4m3x2_to_f16x2(unsigned short v) {
    unsigned r;
    asm("cvt.rn.f16x2.e4m3x2 %0, %1;" : "=r"(r) : "h"(v));
    return r;
}

__device__ __forceinline__ void mma16816(float c[4],
                                         unsigned a0, unsigned a1, unsigned a2, unsigned a3,
                                         unsigned b0, unsigned b1) {
    asm volatile("mma.sync.aligned.m16n8k16.row.col.f32.f16.f16.f32 "
                 "{%0,%1,%2,%3}, {%4,%5,%6,%7}, {%8,%9}, {%0,%1,%2,%3};"
                 : "+f"(c[0]), "+f"(c[1]), "+f"(c[2]), "+f"(c[3])
                 : "r"(a0), "r"(a1), "r"(a2), "r"(a3), "r"(b0), "r"(b1));
}

// ---------------- setup: W1 convert + pool/cnt zero ----------------
__global__ void convert_w_kernel(const float* __restrict__ W1) {
    int t = blockIdx.x * blockDim.x + threadIdx.x;
    if (t < F1 * F1) {
        int n = t >> 7, k = t & 127;
        g_W1h[t] = __float2half(W1[k * F1 + n]);
    }
    if (t < NG * OUTC) g_pool[t] = 0.0f;
    if (t < NG) g_cnt[t] = 0.0f;
    pdl_trigger();
}

// ---------------- GEMM1 (tensor core) + attention dots + self-loop init ----------------
__global__ void gemm1_att_kernel(const float* __restrict__ x,
                                 const float* __restrict__ att_s,
                                 const float* __restrict__ att_d) {
    extern __shared__ __half smem[];
    __half* Wt = smem;                    // [128][WS]
    __half* xs = smem + F1 * WS;          // [64][XS], later reused as output staging
    float* satt = (float*)(xs + 64 * XS); // [256]: att_s | att_d
    float* exs  = satt + 256;             // [64*4] self-loop exp per (row, head)

    int t = threadIdx.x;
    int row0 = blockIdx.x * 64;

    // independent prologue: x tile + att vectors (harness inputs)
    const float4* xv = (const float4*)x;
    for (int i = t; i < 64 * 32; i += 256) {
        int r = i >> 5, c4 = i & 31;
        int gr = row0 + r;
        float4 v = (gr < NN) ? xv[gr * 32 + c4] : make_float4(0, 0, 0, 0);
        __half2 h0 = __floats2half2_rn(v.x, v.y);
        __half2 h1 = __floats2half2_rn(v.z, v.w);
        *(__half2*)&xs[r * XS + c4 * 4]     = h0;
        *(__half2*)&xs[r * XS + c4 * 4 + 2] = h1;
    }
    if (t < 128) { satt[t] = att_s[t]; satt[128 + t] = att_d[t]; }

    pdl_wait();   // g_W1h produced by convert_w

    const uint4* wsrc = (const uint4*)g_W1h;
    for (int i = t; i < F1 * F1 / 8; i += 256) {
        int n = i >> 4, kc = (i & 15) * 8;
        *(uint4*)&Wt[n * WS + kc] = wsrc[i];
    }
    __syncthreads();

    int wid = t >> 5, lane = t & 31;
    int wm = wid & 3, wn = wid >> 2;
    int rq = lane >> 2;
    int q2 = (lane & 3) * 2;
    int rA = wm * 16 + rq;

    float c[8][4];
#pragma unroll
    for (int nt = 0; nt < 8; nt++)
#pragma unroll
        for (int j = 0; j < 4; j++) c[nt][j] = 0.0f;

#pragma unroll
    for (int kb = 0; kb < F1; kb += 16) {
        unsigned a0 = *(unsigned*)&xs[rA * XS + kb + q2];
        unsigned a1 = *(unsigned*)&xs[(rA + 8) * XS + kb + q2];
        unsigned a2 = *(unsigned*)&xs[rA * XS + kb + q2 + 8];
        unsigned a3 = *(unsigned*)&xs[(rA + 8) * XS + kb + q2 + 8];
#pragma unroll
        for (int nt = 0; nt < 8; nt++) {
            int n = wn * 64 + nt * 8 + rq;
            unsigned b0 = *(unsigned*)&Wt[n * WS + kb + q2];
            unsigned b1 = *(unsigned*)&Wt[n * WS + kb + q2 + 8];
            mma16816(c[nt], a0, a1, a2, a3, b0, b1);
        }
    }

    __syncthreads();
    __half* es = xs;
#pragma unroll
    for (int nt = 0; nt < 8; nt++) {
        int col = wn * 64 + nt * 8 + q2;
        *(__half2*)&es[rA * XS + col]       = __floats2half2_rn(c[nt][0], c[nt][1]);
        *(__half2*)&es[(rA + 8) * XS + col] = __floats2half2_rn(c[nt][2], c[nt][3]);
    }
    __syncthreads();

    {
        int row = t >> 2, head = t & 3;
        int grow = row0 + row;
        float s = 0.0f, d = 0.0f;
#pragma unroll
        for (int i = 0; i < 16; i++) {
            float2 f = __half22float2(*(__half2*)&es[row * XS + head * 32 + i * 2]);
            s += f.x * satt[head * 32 + i * 2] + f.y * satt[head * 32 + i * 2 + 1];
            d += f.x * satt[128 + head * 32 + i * 2] + f.y * satt[128 + head * 32 + i * 2 + 1];
        }
        float ex = __expf(lrelu(s + d));
        exs[row * 4 + head] = ex;
        if (grow < NN) {
            g_as1[grow * H1 + head] = s;
            g_ad1[grow * H1 + head] = d;
            g_den1[grow * H1 + head] = ex;
        }
    }
    __syncthreads();

    // h1 fp8 store + acc1 init (= ex_self * h1 in fp16), coalesced
#pragma unroll
    for (int j = 0; j < 4; j++) {
        int idx = t * 4 + j;
        int r2 = idx >> 4, c8 = (idx & 15) * 8;
        int gr = row0 + r2;
        if (gr < NN) {
            uint4 raw = *(uint4*)&es[r2 * XS + c8];
            unsigned* rw = (unsigned*)&raw;
            unsigned short q0 = f16x2_to_e4m3x2(rw[0]);
            unsigned short q1 = f16x2_to_e4m3x2(rw[1]);
            unsigned short q2e = f16x2_to_e4m3x2(rw[2]);
            unsigned short q3 = f16x2_to_e4m3x2(rw[3]);
            uint2 qpack;
            qpack.x = (unsigned)q0 | ((unsigned)q1 << 16);
            qpack.y = (unsigned)q2e | ((unsigned)q3 << 16);
            *(uint2*)&g_h1q[gr * F1 + c8] = qpack;
            __half2 ex2 = __float2half2_rn(exs[r2 * 4 + (c8 >> 5)]);
            __half2 a0 = __hmul2(*(__half2*)&rw[0], ex2);
            __half2 a1 = __hmul2(*(__half2*)&rw[1], ex2);
            __half2 a2 = __hmul2(*(__half2*)&rw[2], ex2);
            __half2 a3 = __hmul2(*(__half2*)&rw[3], ex2);
            uint4 out;
            out.x = *(unsigned*)&a0; out.y = *(unsigned*)&a1;
            out.z = *(unsigned*)&a2; out.w = *(unsigned*)&a3;
            *(uint4*)&g_acc1h[gr * F1 + c8] = out;
        }
    }
    pdl_trigger();
}

// ---------------- edge accumulate layer1: 8 lanes per edge, fp8 gather ----------------
__global__ void edge_acc1_kernel(const int* __restrict__ ei, int E_real) {
    int warp = (blockIdx.x * blockDim.x + threadIdx.x) >> 5;
    int lane = threadIdx.x & 31;
    int sub = lane >> 3;
    int sl  = lane & 7;
    int e = warp * 4 + sub;
    bool act = (e < E_real);

    // independent prologue: edge indices (harness input)
    int v = 0;
    if (lane < 8) {
        int ee = warp * 4 + (lane >> 1);
        if (ee < E_real) v = __ldg(&ei[ee + ((lane & 1) ? E_real : 0)]);
    }
    int s = __shfl_sync(0xffffffffu, v, sub * 2);
    int d = __shfl_sync(0xffffffffu, v, sub * 2 + 1);

    pdl_wait();   // as1/ad1/den1/h1q/acc1h produced by gemm1

    float ex = 0.0f;
    if (act && sl < H1) {
        float val = lrelu(g_as1[s * H1 + sl] + g_ad1[d * H1 + sl]);
        ex = __expf(val);
        atomicAdd(&g_den1[d * H1 + sl], ex);
    }
    float exl = __shfl_sync(0xffffffffu, ex, (lane & ~7) + (sl >> 1));
    __half2 ex2 = __float2half2_rn(exl);

    uint4 q = __ldg((const uint4*)&g_h1q[s * F1 + sl * 16]);
    unsigned w0 = q.x, w1 = q.y, w2 = q.z, w3 = q.w;
    __half2 m[8];
    unsigned f;
    f = e4m3x2_to_f16x2((unsigned short)(w0 & 0xffff)); m[0] = __hmul2(*(__half2*)&f, ex2);
    f = e4m3x2_to_f16x2((unsigned short)(w0 >> 16));    m[1] = __hmul2(*(__half2*)&f, ex2);
    f = e4m3x2_to_f16x2((unsigned short)(w1 & 0xffff)); m[2] = __hmul2(*(__half2*)&f, ex2);
    f = e4m3x2_to_f16x2((unsigned short)(w1 >> 16));    m[3] = __hmul2(*(__half2*)&f, ex2);
    f = e4m3x2_to_f16x2((unsigned short)(w2 & 0xffff)); m[4] = __hmul2(*(__half2*)&f, ex2);
    f = e4m3x2_to_f16x2((unsigned short)(w2 >> 16));    m[5] = __hmul2(*(__half2*)&f, ex2);
    f = e4m3x2_to_f16x2((unsigned short)(w3 & 0xffff)); m[6] = __hmul2(*(__half2*)&f, ex2);
    f = e4m3x2_to_f16x2((unsigned short)(w3 >> 16));    m[7] = __hmul2(*(__half2*)&f, ex2);

    if (act) {
        __half* dst = &g_acc1h[d * F1 + sl * 16];
        asm volatile("red.global.add.noftz.v4.f16x2 [%0], {%1,%2,%3,%4};"
                     :: "l"(dst), "r"(*(unsigned*)&m[0]), "r"(*(unsigned*)&m[1]),
                        "r"(*(unsigned*)&m[2]), "r"(*(unsigned*)&m[3]) : "memory");
        asm volatile("red.global.add.noftz.v4.f16x2 [%0], {%1,%2,%3,%4};"
                     :: "l"(dst + 8), "r"(*(unsigned*)&m[4]), "r"(*(unsigned*)&m[5]),
                        "r"(*(unsigned*)&m[6]), "r"(*(unsigned*)&m[7]) : "memory");
    }
    pdl_trigger();
}

// ---------------- layer2 node: dequant+elu -> mma @W2 -> att2 + self-loop init ----------------
__global__ void l2gemm_kernel(const float* __restrict__ W2,
                              const float* __restrict__ b1,
                              const float* __restrict__ att_s2,
                              const float* __restrict__ att_d2) {
    __shared__ __half hs[64 * XS];
    __shared__ __half w2s[OP * WS];
    __shared__ float es[64 * 20];
    __shared__ float b1s[F1];
    __shared__ float satt[2 * OUTC];

    int t = threadIdx.x;
    int row0 = blockIdx.x * 64;

    // independent prologue: W2 convert (fp32 -> transposed fp16 smem), b1, att2
    for (int i = t; i < OP * F1; i += 256) {
        int n = i >> 7, k = i & 127;
        w2s[n * WS + k] = (n < OUTC) ? __float2half(W2[k * OUTC + n]) : __half(0);
    }
    if (t < F1) b1s[t] = b1[t];
    if (t >= 128 && t < 128 + OUTC) satt[t - 128] = att_s2[t - 128];
    if (t >= 160 && t < 160 + OUTC) satt[OUTC + t - 160] = att_d2[t - 160];

    pdl_wait();   // acc1h/den1 produced by edge_acc1
    __syncthreads();

#pragma unroll
    for (int j = 0; j < 4; j++) {
        int chunk = j * 256 + t;
        int r = chunk >> 4, part = chunk & 15;
        int ch0 = part * 8;
        int gr = row0 + r;
        uint4 raw = make_uint4(0, 0, 0, 0);
        float inv = 0.0f;
        if (gr < NN) {
            raw = *(const uint4*)&g_acc1h[gr * F1 + ch0];
            inv = 1.0f / (g_den1[gr * H1 + (part >> 2)] + 1e-16f);
        }
        const unsigned* rw = (const unsigned*)&raw;
        __half2 outp[4];
#pragma unroll
        for (int q = 0; q < 4; q++) {
            float2 fv = __half22float2(*(__half2*)&rw[q]);
            float h0 = elu_fast(fv.x * inv + b1s[ch0 + q * 2]);
            float h1 = elu_fast(fv.y * inv + b1s[ch0 + q * 2 + 1]);
            outp[q] = __floats2half2_rn(h0, h1);
        }
        *(uint4*)&hs[r * XS + ch0] = *(uint4*)outp;
    }
    __syncthreads();

    int wid = t >> 5, lane = t & 31;
    int wm = wid & 3, wn = wid >> 2;
    int rq = lane >> 2;
    int q2 = (lane & 3) * 2;
    int rA = wm * 16 + rq;

    float c[4] = {0, 0, 0, 0};
#pragma unroll
    for (int kb = 0; kb < F1; kb += 16) {
        unsigned a0 = *(unsigned*)&hs[rA * XS + kb + q2];
        unsigned a1 = *(unsigned*)&hs[(rA + 8) * XS + kb + q2];
        unsigned a2 = *(unsigned*)&hs[rA * XS + kb + q2 + 8];
        unsigned a3 = *(unsigned*)&hs[(rA + 8) * XS + kb + q2 + 8];
        int n = wn * 8 + rq;
        unsigned b0 = *(unsigned*)&w2s[n * WS + kb + q2];
        unsigned b1r = *(unsigned*)&w2s[n * WS + kb + q2 + 8];
        mma16816(c, a0, a1, a2, a3, b0, b1r);
    }
    {
        int col = wn * 8 + q2;
        es[rA * 20 + col]           = c[0];
        es[rA * 20 + col + 1]       = c[1];
        es[(rA + 8) * 20 + col]     = c[2];
        es[(rA + 8) * 20 + col + 1] = c[3];
    }
    __syncthreads();

    if (t < 64) {
        int gr = row0 + t;
        if (gr < NN) {
            float as = 0.0f, ad = 0.0f;
            __half2 pk[8];
#pragma unroll
            for (int c2 = 0; c2 < 8; c2++) {
                float lo = (2 * c2 < OUTC)     ? es[t * 20 + 2 * c2]     : 0.0f;
                float hi = (2 * c2 + 1 < OUTC) ? es[t * 20 + 2 * c2 + 1] : 0.0f;
                pk[c2] = __floats2half2_rn(lo, hi);
                if (2 * c2 < OUTC)     { as += lo * satt[2 * c2];     ad += lo * satt[OUTC + 2 * c2]; }
                if (2 * c2 + 1 < OUTC) { as += hi * satt[2 * c2 + 1]; ad += hi * satt[OUTC + 2 * c2 + 1]; }
            }
            // pack as2/ad2 fp32 bits into padding channels 10-13
            __half2 pks[8];
#pragma unroll
            for (int c2 = 0; c2 < 8; c2++) pks[c2] = pk[c2];
            *(unsigned*)&pks[5] = __float_as_uint(as);   // ch10-11
            *(unsigned*)&pks[6] = __float_as_uint(ad);   // ch12-13
            *(uint4*)&g_h2ph[gr * OP]     = *(uint4*)&pks[0];
            *(uint4*)&g_h2ph[gr * OP + 8] = *(uint4*)&pks[4];
            g_ad2[gr] = ad;
            float ex = __expf(lrelu(as + ad));
            g_den2[gr] = ex;
            __half2 ex2 = __float2half2_rn(ex);
            __half2 ak[8];
#pragma unroll
            for (int c2 = 0; c2 < 5; c2++) ak[c2] = __hmul2(pk[c2], ex2);
            ak[5] = __half2(__half(0), __half(0));
            ak[6] = __half2(__half(0), __half(0));
            ak[7] = __half2(__half(0), __half(0));
            *(uint4*)&g_acc2ph[gr * OP]     = *(uint4*)&ak[0];
            *(uint4*)&g_acc2ph[gr * OP + 8] = *(uint4*)&ak[4];
        }
    }
    pdl_trigger();
}

// ---------------- edge accumulate layer2: 2 lanes per edge, as2 from gather ----------------
__global__ void edge_acc2_kernel(const int* __restrict__ ei, int E_real) {
    int warp = (blockIdx.x * blockDim.x + threadIdx.x) >> 5;
    int lane = threadIdx.x & 31;
    int li = lane & 1;
    int ee = warp * 16 + (lane >> 1);
    bool act = (ee < E_real);

    // independent prologue: edge indices
    int v = 0;
    if (act) v = __ldg(&ei[ee + (li ? E_real : 0)]);
    int s = __shfl_sync(0xffffffffu, v, lane & ~1);
    int d = __shfl_sync(0xffffffffu, v, lane | 1);

    pdl_wait();   // h2ph/ad2/den2/acc2ph produced by l2gemm

    // gather first: li=1's row half carries as2[s] in ch10-11 (raw.y)
    uint4 raw = __ldg((const uint4*)&g_h2ph[s * OP + li * 8]);
    float as2s = __shfl_sync(0xffffffffu, __uint_as_float(raw.y), lane | 1);

    float ex = 0.0f;
    if (act && li == 0) {
        ex = __expf(lrelu(as2s + g_ad2[d]));
        atomicAdd(&g_den2[d], ex);
    }
    ex = __shfl_sync(0xffffffffu, ex, lane & ~1);
    __half2 ex2 = __float2half2_rn(ex);
    __half2 m0 = __hmul2(*(__half2*)&raw.x, ex2);
    __half2 m1, m2;
    __half2 m3 = __hmul2(*(__half2*)&raw.w, ex2);
    if (li == 1) {
        // ch10-13 hold as2/ad2 bits; do not accumulate garbage
        m1 = __half2(__half(0), __half(0));
        m2 = __half2(__half(0), __half(0));
    } else {
        m1 = __hmul2(*(__half2*)&raw.y, ex2);
        m2 = __hmul2(*(__half2*)&raw.z, ex2);
    }
    if (act) {
        __half* dst = &g_acc2ph[d * OP + li * 8];
        asm volatile("red.global.add.noftz.v4.f16x2 [%0], {%1,%2,%3,%4};"
                     :: "l"(dst), "r"(*(unsigned*)&m0), "r"(*(unsigned*)&m1),
                        "r"(*(unsigned*)&m2), "r"(*(unsigned*)&m3) : "memory");
    }
    pdl_trigger();
}

// ---------------- finalize layer2 + pooling + (last block) log_softmax ----------------
__global__ void fin2pool_kernel(const float* __restrict__ b2, const int* __restrict__ batch,
                                float* __restrict__ out) {
    __shared__ unsigned s_last;
    int n = blockIdx.x * blockDim.x + threadIdx.x;
    int t = threadIdx.x;
    int lane = t & 31;
    int g = (n < NN) ? batch[n] : 0;   // independent input

    pdl_wait();   // den2/acc2ph produced by edge_acc2

    if (n < NN) {
        float inv = 1.0f / (g_den2[n] + 1e-16f);
        float v[OUTC];
#pragma unroll
        for (int c = 0; c < OUTC; c++)
            v[c] = elu_fast(__half2float(g_acc2ph[n * OP + c]) * inv + b2[c]);

        int g0 = __shfl_sync(0xffffffffu, g, 0);
        bool uniform = __all_sync(0xffffffffu, g == g0);
        if (uniform) {
#pragma unroll
            for (int o = 16; o; o >>= 1)
#pragma unroll
                for (int c = 0; c < OUTC; c++)
                    v[c] += __shfl_xor_sync(0xffffffffu, v[c], o);
            if (lane == 0) {
#pragma unroll
                for (int c = 0; c < OUTC; c++)
                    atomicAdd(&g_pool[g0 * OUTC + c], v[c]);
                atomicAdd(&g_cnt[g0], 32.0f);
            }
        } else {
#pragma unroll
            for (int c = 0; c < OUTC; c++)
                atomicAdd(&g_pool[g * OUTC + c], v[c]);
            atomicAdd(&g_cnt[g], 1.0f);
        }
    }

    __syncthreads();
    if (t == 0) {
        __threadfence();
        unsigned prev = atomicAdd(&g_done, 1u);
        s_last = (prev == (unsigned)(POOL_BLOCKS - 1)) ? 1u : 0u;
    }
    __syncthreads();
    if (s_last && t < NG) {
        int gg = t;
        float cnt = fmaxf(g_cnt[gg], 1.0f);
        float p[OUTC];
        float mx = -CUDART_INF_F;
#pragma unroll
        for (int c = 0; c < OUTC; c++) {
            p[c] = g_pool[gg * OUTC + c] / cnt;
            mx = fmaxf(mx, p[c]);
        }
        float se = 0.0f;
#pragma unroll
        for (int c = 0; c < OUTC; c++) se += __expf(p[c] - mx);
        float lse = mx + __logf(se);
#pragma unroll
        for (int c = 0; c < OUTC; c++) out[gg * OUTC + c] = p[c] - lse;
        if (gg == 0) g_done = 0;   // reset counter for next launch (graph replay)
    }
}

// ---------------- PDL launch helper ----------------
template <typename F, typename... Args>
static void launch_pdl(F kern, dim3 grid, dim3 block, size_t smem, Args... args) {
    cudaLaunchConfig_t cfg = {};
    cfg.gridDim = grid;
    cfg.blockDim = block;
    cfg.dynamicSmemBytes = smem;
    cudaLaunchAttribute attr[1];
    attr[0].id = cudaLaunchAttributeProgrammaticStreamSerialization;
    attr[0].val.programmaticStreamSerializationAllowed = 1;
    cfg.attrs = attr;
    cfg.numAttrs = 1;
    cudaLaunchKernelEx(&cfg, kern, args...);
}

// ---------------- launch ----------------
extern "C" void kernel_launch(void* const* d_in, const int* in_sizes, int n_in,
                              void* d_out, int out_size) {
    const float* x      = (const float*)d_in[0];
    const float* W1     = (const float*)d_in[1];
    const float* att_s1 = (const float*)d_in[2];
    const float* att_d1 = (const float*)d_in[3];
    const float* b1     = (const float*)d_in[4];
    const float* W2     = (const float*)d_in[5];
    const float* att_s2 = (const float*)d_in[6];
    const float* att_d2 = (const float*)d_in[7];
    const float* b2     = (const float*)d_in[8];
    const int*   ei     = (const int*)d_in[9];
    const int*   batch  = (const int*)d_in[10];
    float* out = (float*)d_out;

    int E_real = in_sizes[9] / 2;

    convert_w_kernel<<<(F1 * F1 + 255) / 256, 256>>>(W1);

    int gemm_smem = (F1 * WS + 64 * XS) * (int)sizeof(__half) + 512 * (int)sizeof(float);
    cudaFuncSetAttribute(gemm1_att_kernel, cudaFuncAttributeMaxDynamicSharedMemorySize, gemm_smem);
    launch_pdl(gemm1_att_kernel, dim3((NN + 63) / 64), dim3(256), (size_t)gemm_smem,
               x, att_s1, att_d1);

    long long w1 = ((long long)E_real + 3) / 4;
    launch_pdl(edge_acc1_kernel, dim3((unsigned)((w1 * 32 + 255) / 256)), dim3(256), (size_t)0,
               ei, E_real);

    launch_pdl(l2gemm_kernel, dim3((NN + 63) / 64), dim3(256), (size_t)0,
               W2, b1, att_s2, att_d2);

    long long w2 = ((long long)E_real + 15) / 16;
    launch_pdl(edge_acc2_kernel, dim3((unsigned)((w2 * 32 + 255) / 256)), dim3(256), (size_t)0,
               ei, E_real);

    launch_pdl(fin2pool_kernel, dim3(POOL_BLOCKS), dim3(256), (size_t)0,
               b2, batch, out);
}